// round 9
// baseline (speedup 1.0000x reference)
#include <cuda_runtime.h>
#include <cstdint>

// KatiesDecoder: out[b, v, u*128:(u+1)*128] = z_prime[b, index[v,u], :]
// z_prime (4, 40962, 128) f32; index (163842, 3) int32; x_ancil unused.
// Output: (4, 163842, 384) f32.
//
// FINAL (roofline-pinned, reproduced 3x at 158.75 us ncu): one warp per (b, v);
// 3 independent gathered LDG.128 (MLP_p1=3, source L2-resident at 21 MB/batch)
// + 3 contiguous streaming STG.128 (__stcs protects z_prime in L2 from the
// 1.007 GB output stream). DRAM 82.7% (6.56 TB/s) with total traffic at the
// 1.04 GB floor -> time floor ~159 us. Falsified variants: MLP=6 pairing
// (+5 us), 2-vertex interleave (+6 us), 192-thread exact tiling (neutral),
// uint32 addressing (+2 us).

static constexpr int B  = 4;
static constexpr int ND = 40962;   // n_dual
static constexpr int D  = 128;     // d_lat
static constexpr int V  = 163842;  // n_vertex
static constexpr int NU = 3;
static constexpr int VEC = D / 4;  // 32 float4 per latent row

static constexpr int Z_ELEMS   = B * ND * D;  // 20,972,544
static constexpr int IDX_ELEMS = V * NU;      // 491,526

static constexpr int WARPS_PER_BLOCK = 8;
static constexpr int THREADS = WARPS_PER_BLOCK * 32;

__global__ void __launch_bounds__(THREADS)
katies_gather_kernel(const float4* __restrict__ z,   // (B, ND, 32) float4
                     const int* __restrict__ idx,    // (V, NU) int32
                     float4* __restrict__ out)       // (B, V, 96) float4
{
    const int v = blockIdx.x * WARPS_PER_BLOCK + (threadIdx.x >> 5);
    if (v >= V) return;
    const int b = blockIdx.y;
    const int lane = threadIdx.x & 31;

    // 3 broadcast index loads (independent of each other).
    const int* ip = idx + v * NU;
    const int j0 = __ldg(ip + 0);
    const int j1 = __ldg(ip + 1);
    const int j2 = __ldg(ip + 2);

    // 3 independent gathered row reads (mostly L2 hits).
    const float4* zb = z + (long long)b * ND * VEC;
    const float4 a0 = __ldg(zb + (long long)j0 * VEC + lane);
    const float4 a1 = __ldg(zb + (long long)j1 * VEC + lane);
    const float4 a2 = __ldg(zb + (long long)j2 * VEC + lane);

    // One contiguous 1536 B destination span per warp.
    float4* dst = out + ((long long)b * V + v) * (NU * VEC) + lane;
    __stcs(dst,           a0);
    __stcs(dst +     VEC, a1);
    __stcs(dst + 2 * VEC, a2);
}

extern "C" void kernel_launch(void* const* d_in, const int* in_sizes, int n_in,
                              void* d_out, int out_size)
{
    // Bind inputs by element count (robust to ordering surprises).
    const void* z_ptr   = d_in[0];
    const void* idx_ptr = d_in[2];
    for (int i = 0; i < n_in; i++) {
        if (in_sizes[i] == Z_ELEMS)   z_ptr   = d_in[i];
        if (in_sizes[i] == IDX_ELEMS) idx_ptr = d_in[i];
    }

    const float4* z   = (const float4*)z_ptr;
    const int*    idx = (const int*)idx_ptr;
    float4*       out = (float4*)d_out;

    dim3 grid((V + WARPS_PER_BLOCK - 1) / WARPS_PER_BLOCK, B);
    katies_gather_kernel<<<grid, THREADS>>>(z, idx, out);
}

// round 10
// speedup vs baseline: 1.0164x; 1.0164x over previous
#include <cuda_runtime.h>
#include <cstdint>

// KatiesDecoder: out[b, v, u*128:(u+1)*128] = z_prime[b, index[v,u], :]
// z_prime (4, 40962, 128) f32; index (163842, 3) int32; x_ancil unused.
// Output: (4, 163842, 384) f32.
//
// FINAL (roofline-pinned, reproduced 4x at 158.7-159.7 us ncu): one warp per
// (b, v); 3 independent gathered LDG.128 (MLP_p1=3, source L2-resident at
// 21 MB/batch) + 3 contiguous streaming STG.128 (__stcs protects z_prime in
// L2 from the 1.007 GB output stream). DRAM ~82.5% (6.5-6.56 TB/s) with total
// traffic at the 1.04 GB floor -> time floor ~159 us = measured.
// Falsified variants: MLP=6 pairing (+5 us), 2-vertex interleave (+6 us),
// 192-thread exact tiling (neutral), uint32 addressing (+2 us).

static constexpr int B  = 4;
static constexpr int ND = 40962;   // n_dual
static constexpr int D  = 128;     // d_lat
static constexpr int V  = 163842;  // n_vertex
static constexpr int NU = 3;
static constexpr int VEC = D / 4;  // 32 float4 per latent row

static constexpr int Z_ELEMS   = B * ND * D;  // 20,972,544
static constexpr int IDX_ELEMS = V * NU;      // 491,526

static constexpr int WARPS_PER_BLOCK = 8;
static constexpr int THREADS = WARPS_PER_BLOCK * 32;

__global__ void __launch_bounds__(THREADS)
katies_gather_kernel(const float4* __restrict__ z,   // (B, ND, 32) float4
                     const int* __restrict__ idx,    // (V, NU) int32
                     float4* __restrict__ out)       // (B, V, 96) float4
{
    const int v = blockIdx.x * WARPS_PER_BLOCK + (threadIdx.x >> 5);
    if (v >= V) return;
    const int b = blockIdx.y;
    const int lane = threadIdx.x & 31;

    // 3 broadcast index loads (independent of each other).
    const int* ip = idx + v * NU;
    const int j0 = __ldg(ip + 0);
    const int j1 = __ldg(ip + 1);
    const int j2 = __ldg(ip + 2);

    // 3 independent gathered row reads (mostly L2 hits).
    const float4* zb = z + (long long)b * ND * VEC;
    const float4 a0 = __ldg(zb + (long long)j0 * VEC + lane);
    const float4 a1 = __ldg(zb + (long long)j1 * VEC + lane);
    const float4 a2 = __ldg(zb + (long long)j2 * VEC + lane);

    // One contiguous 1536 B destination span per warp.
    float4* dst = out + ((long long)b * V + v) * (NU * VEC) + lane;
    __stcs(dst,           a0);
    __stcs(dst +     VEC, a1);
    __stcs(dst + 2 * VEC, a2);
}

extern "C" void kernel_launch(void* const* d_in, const int* in_sizes, int n_in,
                              void* d_out, int out_size)
{
    // Bind inputs by element count (robust to ordering surprises).
    const void* z_ptr   = d_in[0];
    const void* idx_ptr = d_in[2];
    for (int i = 0; i < n_in; i++) {
        if (in_sizes[i] == Z_ELEMS)   z_ptr   = d_in[i];
        if (in_sizes[i] == IDX_ELEMS) idx_ptr = d_in[i];
    }

    const float4* z   = (const float4*)z_ptr;
    const int*    idx = (const int*)idx_ptr;
    float4*       out = (float4*)d_out;

    dim3 grid((V + WARPS_PER_BLOCK - 1) / WARPS_PER_BLOCK, B);
    katies_gather_kernel<<<grid, THREADS>>>(z, idx, out);
}